// round 1
// baseline (speedup 1.0000x reference)
#include <cuda_runtime.h>

// PLE encoding: out[i, j] = 0 if (x<b_lo[j] && j>0), 1 if (x>=b_hi[j] && j<63),
// else (x - b_lo[j]) / (b_hi[j] - b_lo[j]).
// 1M elements x 64 bins = 256 MB f32 output -> pure HBM-store-bound kernel.
// Mapping: one thread per float4 of output (4 consecutive bins of one element)
// so each warp store instruction is a contiguous 512B burst.

#define N_BINS 64
#define VECS_PER_ROW (N_BINS / 4)   // 16 float4 per element

__global__ __launch_bounds__(256) void ple_kernel(
    const float* __restrict__ x,
    const float* __restrict__ bins,
    float4* __restrict__ out,
    int batch)
{
    __shared__ float s_lo[N_BINS];
    __shared__ float s_hi[N_BINS];
    __shared__ float s_inv[N_BINS];

    int tid = threadIdx.x;
    if (tid < N_BINS) {
        float lo = bins[tid];
        float hi = bins[tid + 1];
        s_lo[tid]  = lo;
        s_hi[tid]  = hi;
        s_inv[tid] = 1.0f / (hi - lo);
    }
    __syncthreads();

    long long t = (long long)blockIdx.x * blockDim.x + threadIdx.x;
    long long total = (long long)batch * VECS_PER_ROW;
    if (t >= total) return;

    int i  = (int)(t >> 4);          // element index
    int j0 = ((int)t & 15) << 2;     // first of 4 bins handled by this thread

    float xv = __ldg(&x[i]);

    float r[4];
#pragma unroll
    for (int k = 0; k < 4; k++) {
        int j = j0 + k;
        float lo  = s_lo[j];
        float hi  = s_hi[j];
        float v   = (xv - lo) * s_inv[j];
        // left: x < lo and j > 0  -> 0
        // right: x >= hi and j < 63 -> 1
        bool left  = (xv < lo)  && (j > 0);
        bool right = (xv >= hi) && (j < N_BINS - 1);
        v = left ? 0.0f : v;
        v = right ? 1.0f : v;
        r[k] = v;
    }

    out[t] = make_float4(r[0], r[1], r[2], r[3]);
}

extern "C" void kernel_launch(void* const* d_in, const int* in_sizes, int n_in,
                              void* d_out, int out_size)
{
    const float* x    = (const float*)d_in[0];
    const float* bins = (const float*)d_in[1];
    float4* out       = (float4*)d_out;

    int batch = in_sizes[0];                         // 1,000,000
    long long total_vecs = (long long)batch * VECS_PER_ROW;
    int threads = 256;
    int blocks  = (int)((total_vecs + threads - 1) / threads);

    ple_kernel<<<blocks, threads>>>(x, bins, out, batch);
}

// round 2
// speedup vs baseline: 1.1862x; 1.1862x over previous
#include <cuda_runtime.h>

// PLE encoding, 1M x 64 f32 out (256 MB) -> HBM-store-bound.
// Key identity: reference result per bin j is
//   j==0       : min(v, 1)
//   j==63      : max(v, 0)
//   otherwise  : saturate(v)        where v = (x - lo[j]) / (hi[j] - lo[j])
// (left => v<0 -> 0, right => v>=1 -> 1, mutually exclusive.)
//
// Mapping: thread owns a FIXED 4-bin group (j0 = (t&15)*4), grid-strides over
// elements. Bin params live in registers -> loop body is FFMA+FMNMX+FMNMX per
// bin + one STG.128 per 4 bins. Warp stores are contiguous 512B.

#define N_BINS 64

__global__ __launch_bounds__(256) void ple_kernel(
    const float* __restrict__ x,
    const float* __restrict__ bins,
    float4* __restrict__ out,
    int batch)
{
    const int t       = blockIdx.x * blockDim.x + threadIdx.x;
    const int lane16  = t & 15;
    const int group0  = t >> 4;
    const int ngroups = (gridDim.x * blockDim.x) >> 4;
    const int j0      = lane16 << 2;

    const float NEG_INF = __int_as_float(0xff800000u);
    const float POS_INF = __int_as_float(0x7f800000u);

    // Per-thread bin constants (4 bins), hoisted to registers.
    float inv[4], c[4], lob[4], hib[4];
#pragma unroll
    for (int k = 0; k < 4; k++) {
        const int j  = j0 + k;
        const float lo = __ldg(&bins[j]);
        const float hi = __ldg(&bins[j + 1]);
        const float iv = 1.0f / (hi - lo);
        inv[k] = iv;
        c[k]   = -lo * iv;                       // v = x*inv + c
        lob[k] = (j > 0)          ? 0.0f : NEG_INF;
        hib[k] = (j < N_BINS - 1) ? 1.0f : POS_INF;
    }

#pragma unroll 4
    for (int i = group0; i < batch; i += ngroups) {
        const float xv = __ldg(&x[i]);
        float4 r;
        r.x = fminf(fmaxf(fmaf(xv, inv[0], c[0]), lob[0]), hib[0]);
        r.y = fminf(fmaxf(fmaf(xv, inv[1], c[1]), lob[1]), hib[1]);
        r.z = fminf(fmaxf(fmaf(xv, inv[2], c[2]), lob[2]), hib[2]);
        r.w = fminf(fmaxf(fmaf(xv, inv[3], c[3]), lob[3]), hib[3]);
        out[(long long)i * 16 + lane16] = r;
    }
}

extern "C" void kernel_launch(void* const* d_in, const int* in_sizes, int n_in,
                              void* d_out, int out_size)
{
    const float* x    = (const float*)d_in[0];
    const float* bins = (const float*)d_in[1];
    float4* out       = (float4*)d_out;

    const int batch   = in_sizes[0];   // 1,000,000
    const int threads = 256;
    // Persistent-ish grid: plenty of groups for load balance, each thread
    // loops ~30x so bin-constant setup is amortized.
    const int blocks  = 2048;

    ple_kernel<<<blocks, threads>>>(x, bins, out, batch);
}

// round 3
// speedup vs baseline: 1.3362x; 1.1264x over previous
#include <cuda_runtime.h>

// PLE encoding, 1M x 64 f32 out (256 MB) -> HBM-store-bound.
// Per-bin result identity (verified R1/R2, rel_err ~3e-7):
//   j==0  : min(v, 1)
//   j==63 : max(v, 0)
//   else  : saturate(v),  v = (x - lo[j]) * inv[j]  (FFMA form v = x*inv + c)
//
// R3: 256-bit stores (st.global.v8.f32, Blackwell STG.E.256).
// Thread owns a FIXED 8-bin group (j0=(t&7)*8); warp covers 4 elements with
// perfectly contiguous 1KB stores; bin constants in registers; grid-stride.

#define N_BINS 64

__device__ __forceinline__ void stg256(float* p,
                                       float r0, float r1, float r2, float r3,
                                       float r4, float r5, float r6, float r7)
{
    asm volatile(
        "st.global.v8.f32 [%0], {%1, %2, %3, %4, %5, %6, %7, %8};"
        :: "l"(p),
           "f"(r0), "f"(r1), "f"(r2), "f"(r3),
           "f"(r4), "f"(r5), "f"(r6), "f"(r7)
        : "memory");
}

__global__ __launch_bounds__(256) void ple_kernel(
    const float* __restrict__ x,
    const float* __restrict__ bins,
    float* __restrict__ out,
    int batch)
{
    const int t       = blockIdx.x * blockDim.x + threadIdx.x;
    const int lane8   = t & 7;          // which 8-bin group of the row
    const int group0  = t >> 3;         // starting element index
    const int ngroups = (gridDim.x * blockDim.x) >> 3;
    const int j0      = lane8 << 3;

    const float NEG_INF = __int_as_float(0xff800000u);
    const float POS_INF = __int_as_float(0x7f800000u);

    // Per-thread bin constants for 8 bins, register-resident.
    float inv[8], c[8], lob[8], hib[8];
#pragma unroll
    for (int k = 0; k < 8; k++) {
        const int j  = j0 + k;
        const float lo = __ldg(&bins[j]);
        const float hi = __ldg(&bins[j + 1]);
        const float iv = 1.0f / (hi - lo);
        inv[k] = iv;
        c[k]   = -lo * iv;                       // v = x*inv + c
        lob[k] = (j > 0)          ? 0.0f : NEG_INF;
        hib[k] = (j < N_BINS - 1) ? 1.0f : POS_INF;
    }

#pragma unroll 4
    for (int i = group0; i < batch; i += ngroups) {
        const float xv = __ldg(&x[i]);
        float r[8];
#pragma unroll
        for (int k = 0; k < 8; k++) {
            r[k] = fminf(fmaxf(fmaf(xv, inv[k], c[k]), lob[k]), hib[k]);
        }
        float* p = out + (long long)i * N_BINS + (j0);
        stg256(p, r[0], r[1], r[2], r[3], r[4], r[5], r[6], r[7]);
    }
}

extern "C" void kernel_launch(void* const* d_in, const int* in_sizes, int n_in,
                              void* d_out, int out_size)
{
    const float* x    = (const float*)d_in[0];
    const float* bins = (const float*)d_in[1];
    float* out        = (float*)d_out;

    const int batch   = in_sizes[0];   // 1,000,000
    const int threads = 256;
    const int blocks  = 2048;          // 65536 groups -> ~15 elems/thread

    ple_kernel<<<blocks, threads>>>(x, bins, out, batch);
}